// round 2
// baseline (speedup 1.0000x reference)
#include <cuda_runtime.h>

#define NN 16000
#define KNN 16
#define FIN 32
#define HID 64

// ---------------- scratch (device globals; no allocation allowed) ----------
__device__ float4 g_pts[NN];              // {x, y, x^2+y^2, 0}
__device__ int    g_knn[NN * KNN];        // neighbor (src) indices
__device__ float  g_d  [NN * KNN];        // edge distances
__device__ float  g_ew [NN * KNN];        // normalized inverted distances
__device__ float  g_dis[NN];              // deg^{-1/2}
__device__ unsigned g_minmax[2];          // [0]=min bits, [1]=max bits (d>=0)
__device__ float  g_bufA[NN * HID];       // x@W  buffers
__device__ float  g_bufB[NN * HID];       // h1

// ---------------- prep: pack points, init min/max ---------------------------
__global__ void prep_kernel(const float* __restrict__ c) {
    int i = blockIdx.x * 256 + threadIdx.x;
    if (i == 0) { g_minmax[0] = 0x7F800000u; g_minmax[1] = 0u; }
    if (i < NN) {
        float x = c[2 * i], y = c[2 * i + 1];
        // sq = RN(RN(x*x) + RN(y*y))  (mul-then-reduce, no fma: matches XLA
        // elementwise c*c followed by reduce-add)
        float sq = __fadd_rn(__fmul_rn(x, x), __fmul_rn(y, y));
        g_pts[i] = make_float4(x, y, sq, 0.0f);
    }
}

// ---------------- brute-force exact KNN -------------------------------------
// grid = 500 blocks of 256 threads. Block b owns queries [b*32, b*32+32).
// lane = query within group; warp w scans candidate chunk [w*2000, (w+1)*2000).
// Key = (ordered_uint(d2) << 32) | j  -> smallest-16 == top_k(-d2) incl.
// lower-index tie-break. Merge of 8 partial top-16s via shared memory.
//
// d2 arithmetic bitwise-emulates the reference:
//   dot = fma(y_i, y_j, RN(x_i*x_j))     (fp32 GEMM K-loop fma chain, k=0 then k=1)
//   d2  = RN( RN(sq_i + sq_j) - 2*dot )  (2*dot exact; elementwise ops)
__global__ void knn_kernel() {
    __shared__ unsigned long long sbuf[128][32];   // [slot][query] 32 KB
    const int lane = threadIdx.x & 31;
    const int w    = threadIdx.x >> 5;
    const int q    = blockIdx.x * 32 + lane;

    const float4 me = g_pts[q];

    unsigned long long keys[16];
#pragma unroll
    for (int t = 0; t < 16; t++) keys[t] = ~0ULL;

    const int j0 = w * 2000, j1 = j0 + 2000;
    for (int j = j0; j < j1; j++) {
        float4 p = g_pts[j];                       // same addr across warp
        float dot = __fmaf_rn(me.y, p.y, __fmul_rn(me.x, p.x));
        float d2  = __fsub_rn(__fadd_rn(me.z, p.z), __fmul_rn(2.0f, dot));
        unsigned u = __float_as_uint(d2);
        u = (u & 0x80000000u) ? ~u : (u | 0x80000000u);   // order-preserving map
        unsigned long long key = ((unsigned long long)u << 32) | (unsigned)j;
        if (j != q && key < keys[15]) {
            keys[15] = key;                         // replace worst, bubble down
#pragma unroll
            for (int t = 15; t > 0; t--) {
                if (keys[t] < keys[t - 1]) {
                    unsigned long long tmp = keys[t];
                    keys[t] = keys[t - 1];
                    keys[t - 1] = tmp;
                }
            }
        }
    }

#pragma unroll
    for (int t = 0; t < 16; t++) sbuf[w * 16 + t][lane] = keys[t];
    __syncthreads();

    if (w == 0) {
        // select 16 smallest of the 128 (all keys distinct: idx in low bits)
        unsigned long long last = 0ULL;
        for (int r = 0; r < 16; r++) {
            unsigned long long best = ~0ULL;
            for (int s = 0; s < 128; s++) {
                unsigned long long v = sbuf[s][lane];
                if (v > last && v < best) best = v;
            }
            g_knn[q * KNN + r] = (int)(best & 0xFFFFFFFFULL);
            last = best;
        }
    }
}

// ---------------- edge distances + global min/max ---------------------------
__global__ void edge_kernel(const float* __restrict__ c) {
    __shared__ unsigned smn, smx;
    if (threadIdx.x == 0) { smn = 0x7F800000u; smx = 0u; }
    __syncthreads();
    int e = blockIdx.x * 256 + threadIdx.x;
    if (e < NN * KNN) {
        int t = e >> 4;             // dst (center)
        int s = g_knn[e];           // src (neighbor)
        float dx = __fsub_rn(c[2 * t],     c[2 * s]);
        float dy = __fsub_rn(c[2 * t + 1], c[2 * s + 1]);
        float d  = __fsqrt_rn(__fadd_rn(__fmul_rn(dx, dx), __fmul_rn(dy, dy)));
        g_d[e] = d;
        unsigned b = __float_as_uint(d);   // d >= 0 -> bits are order-preserving
        atomicMin(&smn, b);
        atomicMax(&smx, b);
    }
    __syncthreads();
    if (threadIdx.x == 0) {
        atomicMin(&g_minmax[0], smn);
        atomicMax(&g_minmax[1], smx);
    }
}

// ---------------- edge weights, degree, deg^{-1/2} --------------------------
__global__ void deg_kernel() {
    int n = blockIdx.x * 256 + threadIdx.x;
    if (n >= NN) return;
    float mn = __uint_as_float(g_minmax[0]);
    float mx = __uint_as_float(g_minmax[1]);
    float rng = __fsub_rn(mx, mn);
    float deg = 1.0f;                                 // self-loop weight
#pragma unroll
    for (int k = 0; k < KNN; k++) {
        float ew = __fdiv_rn(__fsub_rn(mx, g_d[n * KNN + k]), rng);
        g_ew[n * KNN + k] = ew;
        deg = __fadd_rn(deg, ew);
    }
    g_dis[n] = rsqrtf(deg);
}

// ---------------- matmuls: X[N,KIN] @ W[KIN,64] -> g_bufA -------------------
template <int KIN, bool FROM_BUFB>
__global__ void mm_kernel(const float* __restrict__ Xin,
                          const float* __restrict__ W) {
    __shared__ float sw[KIN * 64];
    const float* X = FROM_BUFB ? g_bufB : Xin;
    int tid = threadIdx.y * 64 + threadIdx.x;
    for (int i = tid; i < KIN * 64; i += 256) sw[i] = W[i];
    __syncthreads();
    int n = blockIdx.x * 4 + threadIdx.y;
    int f = threadIdx.x;
    const float* xr = X + n * KIN;
    float acc = 0.0f;
#pragma unroll
    for (int k = 0; k < KIN; k++) acc = fmaf(xr[k], sw[k * 64 + f], acc);
    g_bufA[n * 64 + f] = acc;
}

// ---------------- layer-1 aggregation: bufA -> relu(agg + b1) -> bufB -------
__global__ void agg1_kernel(const float* __restrict__ b1) {
    int n = blockIdx.x * 4 + threadIdx.y;
    int f = threadIdx.x;
    float disn = g_dis[n];
    float acc = __fmul_rn(__fmul_rn(disn, disn), g_bufA[n * 64 + f]); // self loop
#pragma unroll
    for (int k = 0; k < KNN; k++) {
        int s = g_knn[n * KNN + k];
        float coef = __fmul_rn(__fmul_rn(g_dis[s], g_ew[n * KNN + k]), disn);
        acc = fmaf(coef, g_bufA[s * 64 + f], acc);
    }
    g_bufB[n * 64 + f] = fmaxf(__fadd_rn(acc, b1[f]), 0.0f);
}

// ---------------- layer-2 aggregation fused with FC head --------------------
__global__ void final_kernel(const float* __restrict__ b2,
                             const float* __restrict__ wfc,
                             const float* __restrict__ bfc,
                             float* __restrict__ y) {
    __shared__ float red[4][64];
    int n = blockIdx.x * 4 + threadIdx.y;
    int f = threadIdx.x;
    float disn = g_dis[n];
    float acc = __fmul_rn(__fmul_rn(disn, disn), g_bufA[n * 64 + f]);
#pragma unroll
    for (int k = 0; k < KNN; k++) {
        int s = g_knn[n * KNN + k];
        float coef = __fmul_rn(__fmul_rn(g_dis[s], g_ew[n * KNN + k]), disn);
        acc = fmaf(coef, g_bufA[s * 64 + f], acc);
    }
    float h2 = fmaxf(__fadd_rn(acc, b2[f]), 0.0f);
    red[threadIdx.y][f] = h2 * wfc[f];
    __syncthreads();
#pragma unroll
    for (int off = 32; off > 0; off >>= 1) {
        if (f < off) red[threadIdx.y][f] += red[threadIdx.y][f + off];
        __syncthreads();
    }
    if (f == 0) y[n] = red[threadIdx.y][0] + bfc[0];
}

// ---------------- launch -----------------------------------------------------
extern "C" void kernel_launch(void* const* d_in, const int* in_sizes, int n_in,
                              void* d_out, int out_size) {
    const float* x   = (const float*)d_in[0];
    const float* c   = (const float*)d_in[1];
    const float* W1  = (const float*)d_in[2];
    const float* b1  = (const float*)d_in[3];
    const float* W2  = (const float*)d_in[4];
    const float* b2  = (const float*)d_in[5];
    const float* Wfc = (const float*)d_in[6];
    const float* bfc = (const float*)d_in[7];
    float* y = (float*)d_out;

    prep_kernel<<<(NN + 255) / 256, 256>>>(c);
    knn_kernel<<<NN / 32, 256>>>();
    edge_kernel<<<(NN * KNN + 255) / 256, 256>>>(c);
    deg_kernel<<<(NN + 255) / 256, 256>>>();

    dim3 blk(64, 4);
    mm_kernel<FIN, false><<<NN / 4, blk>>>(x, W1);   // x @ W1 -> bufA
    agg1_kernel<<<NN / 4, blk>>>(b1);                // -> bufB (h1)
    mm_kernel<HID, true><<<NN / 4, blk>>>(nullptr, W2); // h1 @ W2 -> bufA
    final_kernel<<<NN / 4, blk>>>(b2, Wfc, bfc, y);  // agg2 + relu + FC
}

// round 3
// speedup vs baseline: 12.2237x; 12.2237x over previous
#include <cuda_runtime.h>

#define NN 16000
#define KNN 16
#define FIN 32
#define HID 64
#define G 64
#define NCELL (G * G)

// ---------------- scratch (device globals; no allocation allowed) ----------
__device__ float4 g_pts[NN];              // {x, y, x^2+y^2, 0}
__device__ int    g_knn[NN * KNN];        // neighbor (src) indices
__device__ float  g_d  [NN * KNN];        // edge distances
__device__ float  g_ew [NN * KNN];        // normalized inverted distances
__device__ float  g_dis[NN];              // deg^{-1/2}
__device__ unsigned g_minmax[2];          // [0]=min bits, [1]=max bits (d>=0)
__device__ float  g_bufA[NN * HID];
__device__ float  g_bufB[NN * HID];
// grid structures
__device__ int      g_cnt [NCELL];
__device__ int      g_off [NCELL];        // exclusive prefix offsets
__device__ int      g_fill[NCELL];        // scatter cursors
__device__ int      g_sorted[NN];         // point ids grouped by cell
__device__ unsigned g_bbox[4];            // ordered-uint: minx,maxx,miny,maxy

// ordered-uint map: monotone with float order (handles negatives)
__device__ __forceinline__ unsigned enc_ord(float f) {
    unsigned b = __float_as_uint(f);
    return (b & 0x80000000u) ? ~b : (b | 0x80000000u);
}
__device__ __forceinline__ float dec_ord(unsigned u) {
    return (u & 0x80000000u) ? __uint_as_float(u & 0x7FFFFFFFu)
                             : __uint_as_float(~u);
}

// ---------------- init: bbox/minmax/counters --------------------------------
__global__ void init_kernel() {
    int i = blockIdx.x * 256 + threadIdx.x;
    if (i < NCELL) g_cnt[i] = 0;
    if (i == 0) {
        g_minmax[0] = 0x7F800000u; g_minmax[1] = 0u;
        g_bbox[0] = 0xFFFFFFFFu; g_bbox[1] = 0u;   // minx, maxx
        g_bbox[2] = 0xFFFFFFFFu; g_bbox[3] = 0u;   // miny, maxy
    }
}

// ---------------- prep: pack points + bbox ----------------------------------
__global__ void prep_kernel(const float* __restrict__ c) {
    int i = blockIdx.x * 256 + threadIdx.x;
    if (i >= NN) return;
    float x = c[2 * i], y = c[2 * i + 1];
    float sq = __fadd_rn(__fmul_rn(x, x), __fmul_rn(y, y));
    g_pts[i] = make_float4(x, y, sq, 0.0f);
    atomicMin(&g_bbox[0], enc_ord(x));
    atomicMax(&g_bbox[1], enc_ord(x));
    atomicMin(&g_bbox[2], enc_ord(y));
    atomicMax(&g_bbox[3], enc_ord(y));
}

struct Grid {
    float minx, miny, invsx, invsy, smin;
};
__device__ __forceinline__ Grid load_grid() {
    Grid g;
    g.minx = dec_ord(g_bbox[0]);
    float maxx = dec_ord(g_bbox[1]);
    g.miny = dec_ord(g_bbox[2]);
    float maxy = dec_ord(g_bbox[3]);
    float wx = fmaxf(maxx - g.minx, 1e-20f);
    float wy = fmaxf(maxy - g.miny, 1e-20f);
    g.invsx = (float)G / wx;
    g.invsy = (float)G / wy;
    g.smin  = fminf(wx, wy) / (float)G;
    return g;
}
__device__ __forceinline__ int cell_x(const Grid& g, float x) {
    int c = (int)((x - g.minx) * g.invsx);
    return min(max(c, 0), G - 1);
}
__device__ __forceinline__ int cell_y(const Grid& g, float y) {
    int c = (int)((y - g.miny) * g.invsy);
    return min(max(c, 0), G - 1);
}

// ---------------- histogram --------------------------------------------------
__global__ void hist_kernel() {
    int i = blockIdx.x * 256 + threadIdx.x;
    if (i >= NN) return;
    Grid g = load_grid();
    float4 p = g_pts[i];
    atomicAdd(&g_cnt[cell_y(g, p.y) * G + cell_x(g, p.x)], 1);
}

// ---------------- exclusive scan over 4096 cells (1 block, 1024 thr) --------
__global__ void scan_kernel() {
    __shared__ int sh[1024];
    int t = threadIdx.x;
    int loc[4];
    int s = 0;
#pragma unroll
    for (int i = 0; i < 4; i++) { loc[i] = s; s += g_cnt[t * 4 + i]; }
    sh[t] = s;
    __syncthreads();
    for (int off = 1; off < 1024; off <<= 1) {
        int v = (t >= off) ? sh[t - off] : 0;
        __syncthreads();
        sh[t] += v;
        __syncthreads();
    }
    int excl = (t == 0) ? 0 : sh[t - 1];
#pragma unroll
    for (int i = 0; i < 4; i++) {
        g_off[t * 4 + i]  = excl + loc[i];
        g_fill[t * 4 + i] = excl + loc[i];
    }
}

// ---------------- scatter: counting sort -------------------------------------
__global__ void scatter_kernel() {
    int i = blockIdx.x * 256 + threadIdx.x;
    if (i >= NN) return;
    Grid g = load_grid();
    float4 p = g_pts[i];
    int cell = cell_y(g, p.y) * G + cell_x(g, p.x);
    int pos = atomicAdd(&g_fill[cell], 1);
    g_sorted[pos] = i;
}

// ---------------- exact KNN via expanding grid rings -------------------------
// One thread per query, queries walked in cell-sorted order for warp locality.
// Key = (ordered_uint(computed d2) << 32) | j : identical selection semantics
// to the brute-force version (and to jax top_k(-d2) with low-index ties).
// Stop when geometric ring lower bound exceeds kept-16th computed d2 + margin;
// margin 1e-4 >> max |computed_d2 - true_d2| (~5e-7), so pruning is exact.
__global__ void knn_grid_kernel() {
    int tid = blockIdx.x * 128 + threadIdx.x;
    if (tid >= NN) return;
    const int q = g_sorted[tid];
    const Grid g = load_grid();
    const float4 me = g_pts[q];
    const int cx = cell_x(g, me.x);
    const int cy = cell_y(g, me.y);

    unsigned long long keys[16];
#pragma unroll
    for (int t = 0; t < 16; t++) keys[t] = ~0ULL;

    for (int r = 0; r < G; r++) {
        if (r >= 2) {
            float b = (float)(r - 1) * g.smin;
            float thr = dec_ord((unsigned)(keys[15] >> 32));  // NaN if unfilled
            if (b * b > thr + 1e-4f) break;                   // NaN -> false
        }
        int y0 = cy - r, y1 = cy + r, x0 = cx - r, x1 = cx + r;
        for (int yy = max(y0, 0); yy <= min(y1, G - 1); yy++) {
            bool erow = (yy == y0) || (yy == y1);
            int xstep = (erow || r == 0) ? 1 : 2 * r;
            for (int xx = x0; xx <= x1; xx += xstep) {
                if (xx < 0 || xx >= G) continue;
                int cell = yy * G + xx;
                int p0 = g_off[cell];
                int p1 = p0 + g_cnt[cell];
                for (int p = p0; p < p1; p++) {
                    int j = g_sorted[p];
                    float4 pt = g_pts[j];
                    float dot = __fmaf_rn(me.y, pt.y, __fmul_rn(me.x, pt.x));
                    float d2  = __fsub_rn(__fadd_rn(me.z, pt.z),
                                          __fmul_rn(2.0f, dot));
                    unsigned u = enc_ord(d2);
                    unsigned long long key =
                        ((unsigned long long)u << 32) | (unsigned)j;
                    if (j != q && key < keys[15]) {
                        keys[15] = key;
#pragma unroll
                        for (int t = 15; t > 0; t--) {
                            if (keys[t] < keys[t - 1]) {
                                unsigned long long tmp = keys[t];
                                keys[t] = keys[t - 1];
                                keys[t - 1] = tmp;
                            }
                        }
                    }
                }
            }
        }
    }
#pragma unroll
    for (int t = 0; t < 16; t++)
        g_knn[q * KNN + t] = (int)(keys[t] & 0xFFFFFFFFULL);
}

// ---------------- edge distances + global min/max ---------------------------
__global__ void edge_kernel(const float* __restrict__ c) {
    __shared__ unsigned smn, smx;
    if (threadIdx.x == 0) { smn = 0x7F800000u; smx = 0u; }
    __syncthreads();
    int e = blockIdx.x * 256 + threadIdx.x;
    if (e < NN * KNN) {
        int t = e >> 4;
        int s = g_knn[e];
        float dx = __fsub_rn(c[2 * t],     c[2 * s]);
        float dy = __fsub_rn(c[2 * t + 1], c[2 * s + 1]);
        float d  = __fsqrt_rn(__fadd_rn(__fmul_rn(dx, dx), __fmul_rn(dy, dy)));
        g_d[e] = d;
        unsigned b = __float_as_uint(d);
        atomicMin(&smn, b);
        atomicMax(&smx, b);
    }
    __syncthreads();
    if (threadIdx.x == 0) {
        atomicMin(&g_minmax[0], smn);
        atomicMax(&g_minmax[1], smx);
    }
}

// ---------------- edge weights, degree, deg^{-1/2} --------------------------
__global__ void deg_kernel() {
    int n = blockIdx.x * 256 + threadIdx.x;
    if (n >= NN) return;
    float mn = __uint_as_float(g_minmax[0]);
    float mx = __uint_as_float(g_minmax[1]);
    float rng = __fsub_rn(mx, mn);
    float deg = 1.0f;
#pragma unroll
    for (int k = 0; k < KNN; k++) {
        float ew = __fdiv_rn(__fsub_rn(mx, g_d[n * KNN + k]), rng);
        g_ew[n * KNN + k] = ew;
        deg = __fadd_rn(deg, ew);
    }
    g_dis[n] = rsqrtf(deg);
}

// ---------------- matmuls: X[N,KIN] @ W[KIN,64] -> g_bufA -------------------
template <int KIN, bool FROM_BUFB>
__global__ void mm_kernel(const float* __restrict__ Xin,
                          const float* __restrict__ W) {
    __shared__ float sw[KIN * 64];
    const float* X = FROM_BUFB ? g_bufB : Xin;
    int tid = threadIdx.y * 64 + threadIdx.x;
    for (int i = tid; i < KIN * 64; i += 256) sw[i] = W[i];
    __syncthreads();
    int n = blockIdx.x * 4 + threadIdx.y;
    int f = threadIdx.x;
    const float* xr = X + n * KIN;
    float acc = 0.0f;
#pragma unroll
    for (int k = 0; k < KIN; k++) acc = fmaf(xr[k], sw[k * 64 + f], acc);
    g_bufA[n * 64 + f] = acc;
}

// ---------------- layer-1 aggregation ---------------------------------------
__global__ void agg1_kernel(const float* __restrict__ b1) {
    int n = blockIdx.x * 4 + threadIdx.y;
    int f = threadIdx.x;
    float disn = g_dis[n];
    float acc = __fmul_rn(__fmul_rn(disn, disn), g_bufA[n * 64 + f]);
#pragma unroll
    for (int k = 0; k < KNN; k++) {
        int s = g_knn[n * KNN + k];
        float coef = __fmul_rn(__fmul_rn(g_dis[s], g_ew[n * KNN + k]), disn);
        acc = fmaf(coef, g_bufA[s * 64 + f], acc);
    }
    g_bufB[n * 64 + f] = fmaxf(__fadd_rn(acc, b1[f]), 0.0f);
}

// ---------------- layer-2 aggregation fused with FC head --------------------
__global__ void final_kernel(const float* __restrict__ b2,
                             const float* __restrict__ wfc,
                             const float* __restrict__ bfc,
                             float* __restrict__ y) {
    __shared__ float red[4][64];
    int n = blockIdx.x * 4 + threadIdx.y;
    int f = threadIdx.x;
    float disn = g_dis[n];
    float acc = __fmul_rn(__fmul_rn(disn, disn), g_bufA[n * 64 + f]);
#pragma unroll
    for (int k = 0; k < KNN; k++) {
        int s = g_knn[n * KNN + k];
        float coef = __fmul_rn(__fmul_rn(g_dis[s], g_ew[n * KNN + k]), disn);
        acc = fmaf(coef, g_bufA[s * 64 + f], acc);
    }
    float h2 = fmaxf(__fadd_rn(acc, b2[f]), 0.0f);
    red[threadIdx.y][f] = h2 * wfc[f];
    __syncthreads();
#pragma unroll
    for (int off = 32; off > 0; off >>= 1) {
        if (f < off) red[threadIdx.y][f] += red[threadIdx.y][f + off];
        __syncthreads();
    }
    if (f == 0) y[n] = red[threadIdx.y][0] + bfc[0];
}

// ---------------- launch -----------------------------------------------------
extern "C" void kernel_launch(void* const* d_in, const int* in_sizes, int n_in,
                              void* d_out, int out_size) {
    const float* x   = (const float*)d_in[0];
    const float* c   = (const float*)d_in[1];
    const float* W1  = (const float*)d_in[2];
    const float* b1  = (const float*)d_in[3];
    const float* W2  = (const float*)d_in[4];
    const float* b2  = (const float*)d_in[5];
    const float* Wfc = (const float*)d_in[6];
    const float* bfc = (const float*)d_in[7];
    float* y = (float*)d_out;

    init_kernel<<<NCELL / 256, 256>>>();
    prep_kernel<<<(NN + 255) / 256, 256>>>(c);
    hist_kernel<<<(NN + 255) / 256, 256>>>();
    scan_kernel<<<1, 1024>>>();
    scatter_kernel<<<(NN + 255) / 256, 256>>>();
    knn_grid_kernel<<<(NN + 127) / 128, 128>>>();
    edge_kernel<<<(NN * KNN + 255) / 256, 256>>>(c);
    deg_kernel<<<(NN + 255) / 256, 256>>>();

    dim3 blk(64, 4);
    mm_kernel<FIN, false><<<NN / 4, blk>>>(x, W1);
    agg1_kernel<<<NN / 4, blk>>>(b1);
    mm_kernel<HID, true><<<NN / 4, blk>>>(nullptr, W2);
    final_kernel<<<NN / 4, blk>>>(b2, Wfc, bfc, y);
}

// round 4
// speedup vs baseline: 13.1870x; 1.0788x over previous
#include <cuda_runtime.h>

#define NN 16000
#define KNN 16
#define FIN 32
#define HID 64
#define G 64
#define NCELL (G * G)
#define CAP 32            // max points per cell (lambda ~3.9, max ~16)

// ---------------- scratch (device globals; no allocation allowed) ----------
__device__ float4 g_pts[NN];              // {x, y, x^2+y^2, id-bits}
__device__ float4 g_binpts[NCELL * CAP];  // packed candidates per cell
__device__ int    g_bcnt[NCELL];          // per-cell fill counts
__device__ int    g_knn[NN * KNN];        // neighbor (src) indices
__device__ float  g_d  [NN * KNN];        // edge distances
__device__ float  g_ew [NN * KNN];        // normalized inverted distances
__device__ float  g_dis[NN];              // deg^{-1/2}
__device__ unsigned g_minmax[2];          // [0]=min bits, [1]=max bits (d>=0)
__device__ unsigned g_bbox[4];            // ordered-uint minx,maxx,miny,maxy
__device__ float  g_bufA[NN * HID];       // x@W1
__device__ float  g_bufB[NN * HID];       // h1@W2

// ordered-uint map: monotone with float order (handles negatives)
__device__ __forceinline__ unsigned enc_ord(float f) {
    unsigned b = __float_as_uint(f);
    return (b & 0x80000000u) ? ~b : (b | 0x80000000u);
}
__device__ __forceinline__ float dec_ord(unsigned u) {
    return (u & 0x80000000u) ? __uint_as_float(u & 0x7FFFFFFFu)
                             : __uint_as_float(~u);
}

struct Grid { float minx, miny, invsx, invsy, smin; };
__device__ __forceinline__ Grid load_grid() {
    Grid g;
    g.minx = dec_ord(g_bbox[0]);
    float maxx = dec_ord(g_bbox[1]);
    g.miny = dec_ord(g_bbox[2]);
    float maxy = dec_ord(g_bbox[3]);
    float wx = fmaxf(maxx - g.minx, 1e-20f);
    float wy = fmaxf(maxy - g.miny, 1e-20f);
    g.invsx = (float)G / wx;
    g.invsy = (float)G / wy;
    g.smin  = fminf(wx, wy) / (float)G;
    return g;
}
__device__ __forceinline__ int cell_x(const Grid& g, float x) {
    int c = (int)((x - g.minx) * g.invsx);
    return min(max(c, 0), G - 1);
}
__device__ __forceinline__ int cell_y(const Grid& g, float y) {
    int c = (int)((y - g.miny) * g.invsy);
    return min(max(c, 0), G - 1);
}

// ---------------- K1: init + pack + bbox ------------------------------------
__global__ void prep_kernel(const float* __restrict__ c) {
    int i = blockIdx.x * 256 + threadIdx.x;
    if (i < NCELL) g_bcnt[i] = 0;
    if (i == 0) { g_minmax[0] = 0x7F800000u; g_minmax[1] = 0u;
                  g_bbox[0] = 0xFFFFFFFFu; g_bbox[1] = 0u;
                  g_bbox[2] = 0xFFFFFFFFu; g_bbox[3] = 0u; }
    if (i >= NN) return;
    float x = c[2 * i], y = c[2 * i + 1];
    float sq = __fadd_rn(__fmul_rn(x, x), __fmul_rn(y, y));
    g_pts[i] = make_float4(x, y, sq, __int_as_float(i));
    atomicMin(&g_bbox[0], enc_ord(x));
    atomicMax(&g_bbox[1], enc_ord(x));
    atomicMin(&g_bbox[2], enc_ord(y));
    atomicMax(&g_bbox[3], enc_ord(y));
}

// ---------------- K2: bin fill (blocks < NBF) + x@W1 (rest) -----------------
#define NBF 63
__global__ void fill_mm1_kernel(const float* __restrict__ x,
                                const float* __restrict__ W1) {
    if (blockIdx.x < NBF) {
        int i = blockIdx.x * 256 + threadIdx.x;
        if (i >= NN) return;
        Grid g = load_grid();
        float4 p = g_pts[i];
        int cell = cell_y(g, p.y) * G + cell_x(g, p.x);
        int slot = atomicAdd(&g_bcnt[cell], 1);
        if (slot < CAP) g_binpts[cell * CAP + slot] = p;
        return;
    }
    __shared__ float sw[FIN * 64];
    int tid = threadIdx.x;
    for (int i = tid; i < FIN * 64; i += 256) sw[i] = W1[i];
    __syncthreads();
    int n = (blockIdx.x - NBF) * 4 + (tid >> 6);
    int f = tid & 63;
    const float* xr = x + n * FIN;
    float acc = 0.0f;
#pragma unroll
    for (int k = 0; k < FIN; k++) acc = fmaf(xr[k], sw[k * 64 + f], acc);
    g_bufA[n * 64 + f] = acc;
}

// ---------------- K3: exact KNN (grid rings) + edge distances ---------------
// Key = (ordered_uint(computed d2) << 32) | j  -> min-16 == top_k(-d2) with
// low-index tie-break; selection is order-independent so bin order is moot.
// Ring prune: ((r-1)*cellmin)^2 > kept16_d2 + 1e-4 margin (>> ulp error).
__global__ void knn_edge_kernel() {
    __shared__ unsigned smn, smx;
    if (threadIdx.x == 0) { smn = 0x7F800000u; smx = 0u; }
    __syncthreads();

    const int q = blockIdx.x * 128 + threadIdx.x;
    unsigned long long keys[16];
#pragma unroll
    for (int t = 0; t < 16; t++) keys[t] = ~0ULL;

    if (q < NN) {
        const Grid g = load_grid();
        const float4 me = g_pts[q];
        const int cx = cell_x(g, me.x);
        const int cy = cell_y(g, me.y);

        for (int r = 0; r < G; r++) {
            if (r >= 2) {
                float b = (float)(r - 1) * g.smin;
                float thr = dec_ord((unsigned)(keys[15] >> 32)); // NaN if unfilled
                if (b * b > thr + 1e-4f) break;                  // NaN -> false
            }
            int y0 = cy - r, y1 = cy + r, x0 = cx - r, x1 = cx + r;
            for (int yy = max(y0, 0); yy <= min(y1, G - 1); yy++) {
                bool erow = (yy == y0) || (yy == y1);
                int xstep = (erow || r == 0) ? 1 : 2 * r;
                for (int xx = x0; xx <= x1; xx += xstep) {
                    if (xx < 0 || xx >= G) continue;
                    int cell = yy * G + xx;
                    int cnt = min(g_bcnt[cell], CAP);
                    const float4* bp = &g_binpts[cell * CAP];
                    for (int p = 0; p < cnt; p++) {
                        float4 pt = bp[p];
                        int j = __float_as_int(pt.w);
                        float dot = __fmaf_rn(me.y, pt.y, __fmul_rn(me.x, pt.x));
                        float d2  = __fsub_rn(__fadd_rn(me.z, pt.z),
                                              __fmul_rn(2.0f, dot));
                        unsigned long long key =
                            ((unsigned long long)enc_ord(d2) << 32) | (unsigned)j;
                        if (j != q && key < keys[15]) {
                            keys[15] = key;
#pragma unroll
                            for (int t = 15; t > 0; t--) {
                                if (keys[t] < keys[t - 1]) {
                                    unsigned long long tmp = keys[t];
                                    keys[t] = keys[t - 1];
                                    keys[t - 1] = tmp;
                                }
                            }
                        }
                    }
                }
            }
        }

        // edge epilogue: distances + local minmax
        unsigned lmn = 0x7F800000u, lmx = 0u;
#pragma unroll
        for (int t = 0; t < 16; t++) {
            int j = (int)(keys[t] & 0xFFFFFFFFULL);
            g_knn[q * KNN + t] = j;
            float4 nb = g_pts[j];
            float dx = __fsub_rn(me.x, nb.x);
            float dy = __fsub_rn(me.y, nb.y);
            float d  = __fsqrt_rn(__fadd_rn(__fmul_rn(dx, dx),
                                            __fmul_rn(dy, dy)));
            g_d[q * KNN + t] = d;
            unsigned b = __float_as_uint(d);    // d>=0 -> order-preserving
            lmn = min(lmn, b);
            lmx = max(lmx, b);
        }
        atomicMin(&smn, lmn);
        atomicMax(&smx, lmx);
    }
    __syncthreads();
    if (threadIdx.x == 0) {
        atomicMin(&g_minmax[0], smn);
        atomicMax(&g_minmax[1], smx);
    }
}

// ---------------- K4: edge weights + deg^{-1/2} (1 thread / edge) -----------
__global__ void deg_kernel() {
    int e = blockIdx.x * 256 + threadIdx.x;     // coalesced over edges
    float mx  = __uint_as_float(g_minmax[1]);
    float rng = __fsub_rn(mx, __uint_as_float(g_minmax[0]));
    float ew  = __fdiv_rn(__fsub_rn(mx, g_d[e]), rng);
    g_ew[e] = ew;
    // width-16 shuffle sum -> lane k==0 of each 16-group holds node sum
    float s = ew;
#pragma unroll
    for (int off = 8; off > 0; off >>= 1)
        s += __shfl_down_sync(0xFFFFFFFFu, s, off, 16);
    if ((threadIdx.x & 15) == 0)
        g_dis[e >> 4] = rsqrtf(__fadd_rn(1.0f, s));   // +1 self-loop
}

// ---------------- K5: agg1 + relu + h1@W2 (row-fused) -----------------------
#define NPB 8
__global__ void agg_mm2_kernel(const float* __restrict__ b1,
                               const float* __restrict__ W2) {
    __shared__ float sw[HID * 64];
    __shared__ float sh1[NPB][64];
    int tid = threadIdx.y * 64 + threadIdx.x;
    for (int i = tid; i < HID * 64; i += 64 * NPB) sw[i] = W2[i];
    int n = blockIdx.x * NPB + threadIdx.y;
    int f = threadIdx.x;
    float disn = g_dis[n];
    float acc = __fmul_rn(__fmul_rn(disn, disn), g_bufA[n * 64 + f]);
#pragma unroll
    for (int k = 0; k < KNN; k++) {
        int s = g_knn[n * KNN + k];
        float coef = __fmul_rn(__fmul_rn(g_dis[s], g_ew[n * KNN + k]), disn);
        acc = fmaf(coef, g_bufA[s * 64 + f], acc);
    }
    sh1[threadIdx.y][f] = fmaxf(__fadd_rn(acc, b1[f]), 0.0f);
    __syncthreads();
    float acc2 = 0.0f;
#pragma unroll
    for (int k = 0; k < HID; k++)
        acc2 = fmaf(sh1[threadIdx.y][k], sw[k * 64 + f], acc2);
    g_bufB[n * 64 + f] = acc2;
}

// ---------------- K6: agg2 + relu + FC head ---------------------------------
__global__ void final_kernel(const float* __restrict__ b2,
                             const float* __restrict__ wfc,
                             const float* __restrict__ bfc,
                             float* __restrict__ y) {
    __shared__ float red[NPB][64];
    int n = blockIdx.x * NPB + threadIdx.y;
    int f = threadIdx.x;
    float disn = g_dis[n];
    float acc = __fmul_rn(__fmul_rn(disn, disn), g_bufB[n * 64 + f]);
#pragma unroll
    for (int k = 0; k < KNN; k++) {
        int s = g_knn[n * KNN + k];
        float coef = __fmul_rn(__fmul_rn(g_dis[s], g_ew[n * KNN + k]), disn);
        acc = fmaf(coef, g_bufB[s * 64 + f], acc);
    }
    float h2 = fmaxf(__fadd_rn(acc, b2[f]), 0.0f);
    red[threadIdx.y][f] = h2 * wfc[f];
    __syncthreads();
#pragma unroll
    for (int off = 32; off > 0; off >>= 1) {
        if (f < off) red[threadIdx.y][f] += red[threadIdx.y][f + off];
        __syncthreads();
    }
    if (f == 0) y[n] = red[threadIdx.y][0] + bfc[0];
}

// ---------------- launch -----------------------------------------------------
extern "C" void kernel_launch(void* const* d_in, const int* in_sizes, int n_in,
                              void* d_out, int out_size) {
    const float* x   = (const float*)d_in[0];
    const float* c   = (const float*)d_in[1];
    const float* W1  = (const float*)d_in[2];
    const float* b1  = (const float*)d_in[3];
    const float* W2  = (const float*)d_in[4];
    const float* b2  = (const float*)d_in[5];
    const float* Wfc = (const float*)d_in[6];
    const float* bfc = (const float*)d_in[7];
    float* y = (float*)d_out;

    prep_kernel<<<63, 256>>>(c);
    fill_mm1_kernel<<<NBF + NN / 4, 256>>>(x, W1);
    knn_edge_kernel<<<125, 128>>>();
    deg_kernel<<<NN * KNN / 256, 256>>>();
    dim3 blk(64, NPB);
    agg_mm2_kernel<<<NN / NPB, blk>>>(b1, W2);
    final_kernel<<<NN / NPB, blk>>>(b2, Wfc, bfc, y);
}

// round 6
// speedup vs baseline: 13.6350x; 1.0340x over previous
#include <cuda_runtime.h>

#define NN 16000
#define KNN 16
#define FIN 32
#define HID 64
#define G 64
#define NCELL (G * G)
#define CAP 32            // max points per cell (lambda ~3.9)

// ---------------- scratch (device globals; no allocation allowed) ----------
__device__ float4 g_pts[NN];              // {x, y, x^2+y^2, id-bits}
__device__ float4 g_binpts[NCELL * CAP];  // packed candidates per cell
__device__ int    g_bcnt[NCELL];          // per-cell fill counts
__device__ int    g_knn[NN * KNN];        // neighbor (src) indices (sorted)
__device__ float  g_d  [NN * KNN];        // edge distances
__device__ float  g_ew [NN * KNN];        // normalized inverted distances
__device__ float  g_dis[NN];              // deg^{-1/2}
__device__ unsigned g_minmax[2];          // [0]=min bits, [1]=max bits (d>=0)
__device__ unsigned g_bbox[4];            // ordered-uint minx,maxx,miny,maxy
__device__ float  g_bufA[NN * HID];       // x@W1
__device__ float  g_bufB[NN * HID];       // h1@W2

// ordered-uint map: monotone with float order (handles negatives)
__device__ __forceinline__ unsigned enc_ord(float f) {
    unsigned b = __float_as_uint(f);
    return (b & 0x80000000u) ? ~b : (b | 0x80000000u);
}
__device__ __forceinline__ float dec_ord(unsigned u) {
    return (u & 0x80000000u) ? __uint_as_float(u & 0x7FFFFFFFu)
                             : __uint_as_float(~u);
}

struct Grid { float minx, miny, invsx, invsy, smin; };
__device__ __forceinline__ Grid load_grid() {
    Grid g;
    g.minx = dec_ord(g_bbox[0]);
    float maxx = dec_ord(g_bbox[1]);
    g.miny = dec_ord(g_bbox[2]);
    float maxy = dec_ord(g_bbox[3]);
    float wx = fmaxf(maxx - g.minx, 1e-20f);
    float wy = fmaxf(maxy - g.miny, 1e-20f);
    g.invsx = (float)G / wx;
    g.invsy = (float)G / wy;
    g.smin  = fminf(wx, wy) / (float)G;
    return g;
}
__device__ __forceinline__ int cell_x(const Grid& g, float x) {
    int c = (int)((x - g.minx) * g.invsx);
    return min(max(c, 0), G - 1);
}
__device__ __forceinline__ int cell_y(const Grid& g, float y) {
    int c = (int)((y - g.miny) * g.invsy);
    return min(max(c, 0), G - 1);
}

// ---------------- K1: init + pack + bbox ------------------------------------
__global__ void prep_kernel(const float* __restrict__ c) {
    int i = blockIdx.x * 256 + threadIdx.x;
    if (i < NCELL) g_bcnt[i] = 0;
    if (i == 0) { g_minmax[0] = 0x7F800000u; g_minmax[1] = 0u;
                  g_bbox[0] = 0xFFFFFFFFu; g_bbox[1] = 0u;
                  g_bbox[2] = 0xFFFFFFFFu; g_bbox[3] = 0u; }
    if (i >= NN) return;
    float x = c[2 * i], y = c[2 * i + 1];
    float sq = __fadd_rn(__fmul_rn(x, x), __fmul_rn(y, y));
    g_pts[i] = make_float4(x, y, sq, __int_as_float(i));
    atomicMin(&g_bbox[0], enc_ord(x));
    atomicMax(&g_bbox[1], enc_ord(x));
    atomicMin(&g_bbox[2], enc_ord(y));
    atomicMax(&g_bbox[3], enc_ord(y));
}

// ---------------- K2: bin fill (blocks < NBF) + x@W1 (rest) -----------------
#define NBF 63
__global__ void fill_mm1_kernel(const float* __restrict__ x,
                                const float* __restrict__ W1) {
    if (blockIdx.x < NBF) {
        int i = blockIdx.x * 256 + threadIdx.x;
        if (i >= NN) return;
        Grid g = load_grid();
        float4 p = g_pts[i];
        int cell = cell_y(g, p.y) * G + cell_x(g, p.x);
        int slot = atomicAdd(&g_bcnt[cell], 1);
        if (slot < CAP) g_binpts[cell * CAP + slot] = p;
        return;
    }
    __shared__ float sw[FIN * 64];
    int tid = threadIdx.x;
    for (int i = tid; i < FIN * 64; i += 256) sw[i] = W1[i];
    __syncthreads();
    int n = (blockIdx.x - NBF) * 4 + (tid >> 6);
    int f = tid & 63;
    const float* xr = x + n * FIN;
    float acc = 0.0f;
#pragma unroll
    for (int k = 0; k < FIN; k++) acc = fmaf(xr[k], sw[k * 64 + f], acc);
    g_bufA[n * 64 + f] = acc;
}

// ---------------- K3: exact KNN (grid rings) + edge distances ---------------
// Queries enumerated as (cell, slot) straight from the bins -> warps cover
// adjacent cells (spatial coherence) with no sort pass.
// Selection: min-16 of key=(ordered(d2)<<32|j), tracked UNSORTED via
// branchless replace-max. Slots start at DISTINCT sentinels ~0ULL - t:
// real keys have high word <= 0xFF800000 so they never collide with a
// sentinel, and all keys (incl. sentinels) stay pairwise distinct ->
// "replace the slot equal to cmax" touches exactly one slot every time.
// Final static bubble sort -> output identical to top_k(-d2) low-idx ties.
#define PHA (NCELL * 8 / 256)             // 128
#define PHB (NCELL * 24 / 256)            // 384
__global__ void knn_edge_kernel() {
    __shared__ unsigned smn, smx;
    if (threadIdx.x == 0) { smn = 0x7F800000u; smx = 0u; }
    __syncthreads();

    int cell, slot;
    if (blockIdx.x < PHA) {
        int t = blockIdx.x * 256 + threadIdx.x;
        cell = t >> 3; slot = t & 7;
    } else {
        int t = (blockIdx.x - PHA) * 256 + threadIdx.x;
        cell = t / 24; slot = 8 + t % 24;
    }
    const int cnt0 = min(g_bcnt[cell], CAP);
    const bool active = slot < cnt0;

    if (active) {
        const Grid g = load_grid();
        const float4 me = g_binpts[cell * CAP + slot];
        const int q = __float_as_int(me.w);
        const int cx = cell & (G - 1);
        const int cy = cell >> 6;

        unsigned long long keys[16];
#pragma unroll
        for (int t = 0; t < 16; t++) keys[t] = ~0ULL - (unsigned long long)t;
        unsigned long long cmax = ~0ULL;

        for (int r = 0; r < G; r++) {
            if (r >= 2) {
                float b = (float)(r - 1) * g.smin;
                float thr = dec_ord((unsigned)(cmax >> 32)); // NaN if sentinel
                if (b * b > thr + 1e-4f) break;              // NaN -> false
            }
            int y0 = cy - r, y1 = cy + r, x0 = cx - r, x1 = cx + r;
            for (int yy = max(y0, 0); yy <= min(y1, G - 1); yy++) {
                bool erow = (yy == y0) || (yy == y1);
                int xstep = (erow || r == 0) ? 1 : 2 * r;
                for (int xx = x0; xx <= x1; xx += xstep) {
                    if (xx < 0 || xx >= G) continue;
                    int cc = yy * G + xx;
                    int cnt = min(g_bcnt[cc], CAP);
                    const float4* bp = &g_binpts[cc * CAP];
                    for (int p = 0; p < cnt; p++) {
                        float4 pt = bp[p];
                        int j = __float_as_int(pt.w);
                        float dot = __fmaf_rn(me.y, pt.y,
                                              __fmul_rn(me.x, pt.x));
                        float d2  = __fsub_rn(__fadd_rn(me.z, pt.z),
                                              __fmul_rn(2.0f, dot));
                        unsigned long long key =
                            ((unsigned long long)enc_ord(d2) << 32) |
                            (unsigned)j;
                        if (j != q && key < cmax) {
                            unsigned long long nm = 0ULL;
#pragma unroll
                            for (int t = 0; t < 16; t++) {
                                if (keys[t] == cmax) keys[t] = key;
                                nm = max(nm, keys[t]);
                            }
                            cmax = nm;
                        }
                    }
                }
            }
        }

        // sort 16 keys ascending (static bubble network, registers only)
#pragma unroll
        for (int i = 0; i < 15; i++)
#pragma unroll
            for (int t = 0; t < 15 - i; t++)
                if (keys[t] > keys[t + 1]) {
                    unsigned long long tmp = keys[t];
                    keys[t] = keys[t + 1];
                    keys[t + 1] = tmp;
                }

        // edge epilogue: distances + local minmax
        unsigned lmn = 0x7F800000u, lmx = 0u;
#pragma unroll
        for (int t = 0; t < 16; t++) {
            int j = (int)(keys[t] & 0xFFFFFFFFULL);
            g_knn[q * KNN + t] = j;
            float4 nb = g_pts[j];
            float dx = __fsub_rn(me.x, nb.x);
            float dy = __fsub_rn(me.y, nb.y);
            float d  = __fsqrt_rn(__fadd_rn(__fmul_rn(dx, dx),
                                            __fmul_rn(dy, dy)));
            g_d[q * KNN + t] = d;
            unsigned b = __float_as_uint(d);    // d>=0 -> order-preserving
            lmn = min(lmn, b);
            lmx = max(lmx, b);
        }
        atomicMin(&smn, lmn);
        atomicMax(&smx, lmx);
    }
    __syncthreads();
    if (threadIdx.x == 0) {
        atomicMin(&g_minmax[0], smn);
        atomicMax(&g_minmax[1], smx);
    }
}

// ---------------- K4: edge weights + deg^{-1/2} (1 thread / edge) -----------
__global__ void deg_kernel() {
    int e = blockIdx.x * 256 + threadIdx.x;     // coalesced over edges
    float mx  = __uint_as_float(g_minmax[1]);
    float rng = __fsub_rn(mx, __uint_as_float(g_minmax[0]));
    float ew  = __fdiv_rn(__fsub_rn(mx, g_d[e]), rng);
    g_ew[e] = ew;
    float s = ew;
#pragma unroll
    for (int off = 8; off > 0; off >>= 1)
        s += __shfl_down_sync(0xFFFFFFFFu, s, off, 16);
    if ((threadIdx.x & 15) == 0)
        g_dis[e >> 4] = rsqrtf(__fadd_rn(1.0f, s));   // +1 self-loop
}

// ---------------- K5: agg1 + relu + h1@W2 (row-fused) -----------------------
#define NPB 8
__global__ void agg_mm2_kernel(const float* __restrict__ b1,
                               const float* __restrict__ W2) {
    __shared__ float sw[HID * 64];
    __shared__ float sh1[NPB][64];
    int tid = threadIdx.y * 64 + threadIdx.x;
    for (int i = tid; i < HID * 64; i += 64 * NPB) sw[i] = W2[i];
    int n = blockIdx.x * NPB + threadIdx.y;
    int f = threadIdx.x;
    float disn = g_dis[n];
    float acc = __fmul_rn(__fmul_rn(disn, disn), g_bufA[n * 64 + f]);
#pragma unroll
    for (int k = 0; k < KNN; k++) {
        int s = g_knn[n * KNN + k];
        float coef = __fmul_rn(__fmul_rn(g_dis[s], g_ew[n * KNN + k]), disn);
        acc = fmaf(coef, g_bufA[s * 64 + f], acc);
    }
    sh1[threadIdx.y][f] = fmaxf(__fadd_rn(acc, b1[f]), 0.0f);
    __syncthreads();
    float acc2 = 0.0f;
#pragma unroll
    for (int k = 0; k < HID; k++)
        acc2 = fmaf(sh1[threadIdx.y][k], sw[k * 64 + f], acc2);
    g_bufB[n * 64 + f] = acc2;
}

// ---------------- K6: agg2 + relu + FC head ---------------------------------
__global__ void final_kernel(const float* __restrict__ b2,
                             const float* __restrict__ wfc,
                             const float* __restrict__ bfc,
                             float* __restrict__ y) {
    __shared__ float red[NPB][64];
    int n = blockIdx.x * NPB + threadIdx.y;
    int f = threadIdx.x;
    float disn = g_dis[n];
    float acc = __fmul_rn(__fmul_rn(disn, disn), g_bufB[n * 64 + f]);
#pragma unroll
    for (int k = 0; k < KNN; k++) {
        int s = g_knn[n * KNN + k];
        float coef = __fmul_rn(__fmul_rn(g_dis[s], g_ew[n * KNN + k]), disn);
        acc = fmaf(coef, g_bufB[s * 64 + f], acc);
    }
    float h2 = fmaxf(__fadd_rn(acc, b2[f]), 0.0f);
    red[threadIdx.y][f] = h2 * wfc[f];
    __syncthreads();
#pragma unroll
    for (int off = 32; off > 0; off >>= 1) {
        if (f < off) red[threadIdx.y][f] += red[threadIdx.y][f + off];
        __syncthreads();
    }
    if (f == 0) y[n] = red[threadIdx.y][0] + bfc[0];
}

// ---------------- launch -----------------------------------------------------
extern "C" void kernel_launch(void* const* d_in, const int* in_sizes, int n_in,
                              void* d_out, int out_size) {
    const float* x   = (const float*)d_in[0];
    const float* c   = (const float*)d_in[1];
    const float* W1  = (const float*)d_in[2];
    const float* b1  = (const float*)d_in[3];
    const float* W2  = (const float*)d_in[4];
    const float* b2  = (const float*)d_in[5];
    const float* Wfc = (const float*)d_in[6];
    const float* bfc = (const float*)d_in[7];
    float* y = (float*)d_out;

    prep_kernel<<<63, 256>>>(c);
    fill_mm1_kernel<<<NBF + NN / 4, 256>>>(x, W1);
    knn_edge_kernel<<<PHA + PHB, 256>>>();
    deg_kernel<<<NN * KNN / 256, 256>>>();
    dim3 blk(64, NPB);
    agg_mm2_kernel<<<NN / NPB, blk>>>(b1, W2);
    final_kernel<<<NN / NPB, blk>>>(b2, Wfc, bfc, y);
}